// round 13
// baseline (speedup 1.0000x reference)
#include <cuda_runtime.h>
#include <cuda_bf16.h>
#include <cstdint>

#define NN 100000
#define NE 1600000
#define C  128        // IN_CH == HEADS*OUT_CH == 128
#define MT 64         // rows per CTA
#define NBLK ((NN + MT - 1) / MT)   // 1563

// ---------------- device globals ----------------
__device__ int g_mark[NN];
// Pre-split, pre-transposed, pre-swizzled W tile: hi at [0,32K), lo at [32K,64K)
__device__ __align__(16) char g_wt[65536];

__global__ void k_zero4() {
    int i = blockIdx.x * 256 + threadIdx.x;
    if (i * 4 < NN) *(int4*)(g_mark + i * 4) = make_int4(0, 0, 0, 0);  // NN%4==0
}

__global__ void k_mark(const int* __restrict__ col) {
    int e = blockIdx.x * 256 + threadIdx.x;
    if (e < NE) {
        int n = col[e];
        if (n >= 0 && n < NN) g_mark[n] = 1;
    }
}

// Zero rows with zero in-degree (rare: ~NN*e^-16 ~ 0 rows). Joins mark + gemm.
__global__ void k_apply(float* __restrict__ out) {
    int n = blockIdx.x * 256 + threadIdx.x;
    if (n < NN && !g_mark[n]) {
        float4 z = make_float4(0.f, 0.f, 0.f, 0.f);
        float4* p = (float4*)(out + (size_t)n * C);
        #pragma unroll
        for (int i = 0; i < 32; i++) p[i] = z;
    }
}

// ---------------- helpers ----------------
__device__ __forceinline__ uint32_t smem_u32(const void* p) {
    uint32_t a;
    asm("{ .reg .u64 t; cvta.to.shared.u64 t, %1; cvt.u32.u64 %0, t; }"
        : "=r"(a) : "l"(p));
    return a;
}

__device__ __forceinline__ void cp16(uint32_t dst, const void* src) {
    asm volatile("cp.async.cg.shared.global [%0], [%1], 16;"
                 :: "r"(dst), "l"(__cvta_generic_to_global(src)) : "memory");
}

#define LDSM_X4(r, addr) \
    asm volatile("ldmatrix.sync.aligned.m8n8.x4.shared.b16 {%0,%1,%2,%3}, [%4];" \
        : "=r"((r)[0]), "=r"((r)[1]), "=r"((r)[2]), "=r"((r)[3]) : "r"(addr))

__device__ __forceinline__ void mma16816(float* c, const uint32_t* a,
                                         uint32_t b0, uint32_t b1) {
    asm volatile(
        "mma.sync.aligned.m16n8k16.row.col.f32.bf16.bf16.f32 "
        "{%0,%1,%2,%3}, {%4,%5,%6,%7}, {%8,%9}, {%0,%1,%2,%3};"
        : "+f"(c[0]), "+f"(c[1]), "+f"(c[2]), "+f"(c[3])
        : "r"(a[0]), "r"(a[1]), "r"(a[2]), "r"(a[3]), "r"(b0), "r"(b1));
}

union BF2U { __nv_bfloat162 b; uint32_t u; };

__device__ __forceinline__ void split_pack2(float4 v, uint2& hi, uint2& lo) {
    __nv_bfloat16 h0 = __float2bfloat16(v.x), h1 = __float2bfloat16(v.y),
                  h2 = __float2bfloat16(v.z), h3 = __float2bfloat16(v.w);
    __nv_bfloat16 l0 = __float2bfloat16(v.x - __bfloat162float(h0));
    __nv_bfloat16 l1 = __float2bfloat16(v.y - __bfloat162float(h1));
    __nv_bfloat16 l2 = __float2bfloat16(v.z - __bfloat162float(h2));
    __nv_bfloat16 l3 = __float2bfloat16(v.w - __bfloat162float(h3));
    BF2U a, b, c, d;
    a.b = __nv_bfloat162(h0, h1); b.b = __nv_bfloat162(h2, h3);
    c.b = __nv_bfloat162(l0, l1); d.b = __nv_bfloat162(l2, l3);
    hi = make_uint2(a.u, b.u);
    lo = make_uint2(c.u, d.u);
}

// Pre-split W: Wt[n][k] = w[k][n], bf16 hi/lo, swizzled exactly like the smem
// layout (row stride 256B, 16B-chunk XOR swizzle). 16 blocks x 256 threads.
__global__ void k_prep(const float* __restrict__ w) {
    int idx = blockIdx.x * 256 + threadIdx.x;   // 0..4095
    int n  = idx & 127;
    int k0 = (idx >> 7) * 4;
    float4 v;
    v.x = w[(size_t)(k0 + 0) * C + n];
    v.y = w[(size_t)(k0 + 1) * C + n];
    v.z = w[(size_t)(k0 + 2) * C + n];
    v.w = w[(size_t)(k0 + 3) * C + n];
    uint2 hi, lo;
    split_pack2(v, hi, lo);
    uint32_t off = n * 256 + ((k0 * 2) ^ ((n & 7) << 4));
    *(uint2*)(g_wt + off)         = hi;
    *(uint2*)(g_wt + 32768 + off) = lo;
}

// SMEM layout (bytes). Row stride 256B, XOR swizzle byteoff ^ ((row&7)<<4).
#define SM_AH 0                  // A hi: 64 x 128 bf16 = 16 KB
#define SM_AL 16384              // A lo
#define SM_BH 32768              // Wt hi+lo contiguous 64 KB (mirrors g_wt)
#define SM_BL 65536
#define SM_TOTAL 98304           // 96 KB -> 2 CTAs / SM

// out[m,n] = sum_k x[m,k]*w[k,n]  (UNMASKED; k_apply zeroes deg-0 rows)
// 3-pass split-bf16: Ahi*Bhi + Ahi*Blo + Alo*Bhi (fp32 accum)
// 4 warps (2 wm x 2 wn), warp tile 32x64 -> 48 LDSM_X4 per CTA-kstep (was 64).
__global__ void __launch_bounds__(128, 2) k_tc(
    const float* __restrict__ x, float* __restrict__ out)
{
    extern __shared__ char smem[];
    const uint32_t sb = smem_u32(smem);
    const int tid = threadIdx.x;
    const int l   = tid & 31;
    const int wid = tid >> 5;
    const int wm  = wid >> 1;          // 0..1 : rows wm*32 ..
    const int wn  = wid & 1;           // 0..1 : cols wn*64 ..
    const int m0  = blockIdx.x * MT;

    // ---- B tile: flat async copy of pre-split/pre-swizzled Wt (64 KB)
    #pragma unroll
    for (int i = 0; i < 32; i++) {
        int c16 = tid + 128 * i;                  // 16B chunk index, 0..4095
        cp16(sb + SM_BH + c16 * 16, g_wt + c16 * 16);
    }
    asm volatile("cp.async.commit_group;" ::: "memory");

    // ---- A tile: coalesced f32 loads, split to bf16 hi/lo, swizzled store
    #pragma unroll
    for (int it = 0; it < 16; it++) {
        int i   = tid + 128 * it;
        int row = i >> 5;
        int c4  = i & 31;
        int gm  = m0 + row;
        float4 v = make_float4(0.f, 0.f, 0.f, 0.f);
        if (gm < NN) v = *(const float4*)(x + (size_t)gm * C + 4 * c4);
        uint2 hi, lo;
        split_pack2(v, hi, lo);
        uint32_t off = row * 256 + ((c4 * 8) ^ ((row & 7) << 4));
        *(uint2*)(smem + SM_AH + off) = hi;
        *(uint2*)(smem + SM_AL + off) = lo;
    }

    asm volatile("cp.async.wait_group 0;" ::: "memory");
    __syncthreads();

    // ---- per-lane ldmatrix address components
    const uint32_t aRow = (l & 7) + ((l >> 3) & 1) * 8;
    const uint32_t aK16 = (l >> 4) * 16;
    const uint32_t bN   = (l & 7) + ((l >> 4) & 1) * 8;
    const uint32_t bK16 = ((l >> 3) & 1) * 16;
    const uint32_t swz  = (l & 7) << 4;
    const uint32_t aOff0 = (wm * 32 + aRow) * 256;
    const uint32_t bOff0 = (wn * 64 + bN) * 256;

    float acc[2][8][4];
    #pragma unroll
    for (int mt = 0; mt < 2; mt++)
        #pragma unroll
        for (int nt = 0; nt < 8; nt++)
            #pragma unroll
            for (int i = 0; i < 4; i++) acc[mt][nt][i] = 0.f;

    #pragma unroll
    for (int ks = 0; ks < 8; ks++) {
        const uint32_t kbA = ((uint32_t)(ks * 32) + aK16) ^ swz;
        const uint32_t kbB = ((uint32_t)(ks * 32) + bK16) ^ swz;

        uint32_t ah[2][4], al[2][4], bh[4][4], bl[4][4];
        #pragma unroll
        for (int mt = 0; mt < 2; mt++) {
            uint32_t adr = sb + SM_AH + aOff0 + mt * 4096 + kbA;
            LDSM_X4(ah[mt], adr);
            LDSM_X4(al[mt], adr + (SM_AL - SM_AH));
        }
        #pragma unroll
        for (int np = 0; np < 4; np++) {
            uint32_t adr = sb + SM_BH + bOff0 + np * 4096 + kbB;
            LDSM_X4(bh[np], adr);
            LDSM_X4(bl[np], adr + (SM_BL - SM_BH));
        }

        #pragma unroll
        for (int mt = 0; mt < 2; mt++)
            #pragma unroll
            for (int nt = 0; nt < 8; nt++) {
                uint32_t bh0 = bh[nt >> 1][(nt & 1) * 2];
                uint32_t bh1 = bh[nt >> 1][(nt & 1) * 2 + 1];
                uint32_t bl0 = bl[nt >> 1][(nt & 1) * 2];
                uint32_t bl1 = bl[nt >> 1][(nt & 1) * 2 + 1];
                mma16816(acc[mt][nt], ah[mt], bh0, bh1);   // hi*hi
                mma16816(acc[mt][nt], ah[mt], bl0, bl1);   // hi*lo
                mma16816(acc[mt][nt], al[mt], bh0, bh1);   // lo*hi
            }
    }

    // ---- epilogue: store (no mask here; k_apply handles deg-0 rows)
    #pragma unroll
    for (int mt = 0; mt < 2; mt++) {
        int r0 = m0 + wm * 32 + mt * 16 + (l >> 2);
        int r1 = r0 + 8;
        #pragma unroll
        for (int nt = 0; nt < 8; nt++) {
            int colc = wn * 64 + nt * 8 + (l & 3) * 2;
            if (r0 < NN)
                *(float2*)(out + (size_t)r0 * C + colc) =
                    make_float2(acc[mt][nt][0], acc[mt][nt][1]);
            if (r1 < NN)
                *(float2*)(out + (size_t)r1 * C + colc) =
                    make_float2(acc[mt][nt][2], acc[mt][nt][3]);
        }
    }
}

extern "C" void kernel_launch(void* const* d_in, const int* in_sizes, int n_in,
                              void* d_out, int out_size) {
    // Identify inputs by element count (robust to metadata ordering):
    //   x: 12,800,000 f32 | weight: 16,384 f32 | att: 256 f32 (irrelevant —
    //   softmax weights sum to 1 over segments keyed identically to the
    //   message source, so attention collapses to an in-degree mask)
    //   edge_index: 3,200,000 int32
    const float* x = nullptr;
    const float* w = nullptr;
    const int*   ei = nullptr;
    for (int i = 0; i < n_in; i++) {
        if (in_sizes[i] == NN * C)      x  = (const float*)d_in[i];
        else if (in_sizes[i] == C * C)  w  = (const float*)d_in[i];
        else if (in_sizes[i] == 2 * NE) ei = (const int*)d_in[i];
    }
    const int* col = ei + NE;
    float* out = (float*)d_out;

    // One-time resources (no device memory allocation involved)
    static cudaStream_t s2;
    static cudaEvent_t ev_fork, ev_mark;
    static bool init = false;
    if (!init) {
        cudaFuncSetAttribute(k_tc, cudaFuncAttributeMaxDynamicSharedMemorySize,
                             SM_TOTAL);
        cudaStreamCreateWithFlags(&s2, cudaStreamNonBlocking);
        cudaEventCreateWithFlags(&ev_fork, cudaEventDisableTiming);
        cudaEventCreateWithFlags(&ev_mark, cudaEventDisableTiming);
        init = true;
    }

    // Fork: mark chain on s2, prep+GEMM on the main (capture) stream.
    cudaEventRecord(ev_fork, 0);
    cudaStreamWaitEvent(s2, ev_fork, 0);
    k_zero4<<<(NN / 4 + 255) / 256, 256, 0, s2>>>();
    k_mark<<<(NE + 255) / 256, 256, 0, s2>>>(col);
    cudaEventRecord(ev_mark, s2);

    k_prep<<<16, 256>>>(w);
    k_tc<<<NBLK, 128, SM_TOTAL>>>(x, out);

    // Join: apply in-degree mask after both the GEMM and the mark chain.
    cudaStreamWaitEvent(0, ev_mark, 0);
    k_apply<<<(NN + 255) / 256, 256>>>(out);
}

// round 14
// speedup vs baseline: 1.3732x; 1.3732x over previous
#include <cuda_runtime.h>
#include <cuda_bf16.h>
#include <cstdint>

#define NN 100000
#define NE 1600000
#define C  128        // IN_CH == HEADS*OUT_CH == 128
#define MT 64         // rows per CTA
#define NBLK ((NN + MT - 1) / MT)   // 1563

// ---------------- device globals ----------------
__device__ int g_mark[NN];
// Pre-split, pre-transposed, pre-swizzled W tile: hi at [0,32K), lo at [32K,64K)
__device__ __align__(16) char g_wt[65536];

__global__ void k_zero4() {
    int i = blockIdx.x * 256 + threadIdx.x;
    if (i * 4 < NN) *(int4*)(g_mark + i * 4) = make_int4(0, 0, 0, 0);  // NN%4==0
}

__global__ void k_mark(const int* __restrict__ col) {
    int e = blockIdx.x * 256 + threadIdx.x;
    if (e < NE) {
        int n = col[e];
        if (n >= 0 && n < NN) g_mark[n] = 1;
    }
}

// Zero rows with zero in-degree (rare: ~0 rows expected). Joins mark + gemm.
__global__ void k_apply(float* __restrict__ out) {
    int n = blockIdx.x * 256 + threadIdx.x;
    if (n < NN && !g_mark[n]) {
        float4 z = make_float4(0.f, 0.f, 0.f, 0.f);
        float4* p = (float4*)(out + (size_t)n * C);
        #pragma unroll
        for (int i = 0; i < 32; i++) p[i] = z;
    }
}

// ---------------- helpers ----------------
__device__ __forceinline__ uint32_t smem_u32(const void* p) {
    uint32_t a;
    asm("{ .reg .u64 t; cvta.to.shared.u64 t, %1; cvt.u32.u64 %0, t; }"
        : "=r"(a) : "l"(p));
    return a;
}

__device__ __forceinline__ void cp16(uint32_t dst, const void* src) {
    asm volatile("cp.async.cg.shared.global [%0], [%1], 16;"
                 :: "r"(dst), "l"(__cvta_generic_to_global(src)) : "memory");
}

#define LDSM_X4(r, addr) \
    asm volatile("ldmatrix.sync.aligned.m8n8.x4.shared.b16 {%0,%1,%2,%3}, [%4];" \
        : "=r"((r)[0]), "=r"((r)[1]), "=r"((r)[2]), "=r"((r)[3]) : "r"(addr))

__device__ __forceinline__ void mma16816(float* c, const uint32_t* a,
                                         uint32_t b0, uint32_t b1) {
    asm volatile(
        "mma.sync.aligned.m16n8k16.row.col.f32.bf16.bf16.f32 "
        "{%0,%1,%2,%3}, {%4,%5,%6,%7}, {%8,%9}, {%0,%1,%2,%3};"
        : "+f"(c[0]), "+f"(c[1]), "+f"(c[2]), "+f"(c[3])
        : "r"(a[0]), "r"(a[1]), "r"(a[2]), "r"(a[3]), "r"(b0), "r"(b1));
}

union BF2U { __nv_bfloat162 b; uint32_t u; };

__device__ __forceinline__ void split_pack2(float4 v, uint2& hi, uint2& lo) {
    __nv_bfloat16 h0 = __float2bfloat16(v.x), h1 = __float2bfloat16(v.y),
                  h2 = __float2bfloat16(v.z), h3 = __float2bfloat16(v.w);
    __nv_bfloat16 l0 = __float2bfloat16(v.x - __bfloat162float(h0));
    __nv_bfloat16 l1 = __float2bfloat16(v.y - __bfloat162float(h1));
    __nv_bfloat16 l2 = __float2bfloat16(v.z - __bfloat162float(h2));
    __nv_bfloat16 l3 = __float2bfloat16(v.w - __bfloat162float(h3));
    BF2U a, b, c, d;
    a.b = __nv_bfloat162(h0, h1); b.b = __nv_bfloat162(h2, h3);
    c.b = __nv_bfloat162(l0, l1); d.b = __nv_bfloat162(l2, l3);
    hi = make_uint2(a.u, b.u);
    lo = make_uint2(c.u, d.u);
}

// Pre-split W: Wt[n][k] = w[k][n], bf16 hi/lo, swizzled exactly like the smem
// layout (row stride 256B, 16B-chunk XOR swizzle). 16 blocks x 256 threads.
__global__ void k_prep(const float* __restrict__ w) {
    int idx = blockIdx.x * 256 + threadIdx.x;   // 0..4095
    int n  = idx & 127;
    int k0 = (idx >> 7) * 4;
    float4 v;
    v.x = w[(size_t)(k0 + 0) * C + n];
    v.y = w[(size_t)(k0 + 1) * C + n];
    v.z = w[(size_t)(k0 + 2) * C + n];
    v.w = w[(size_t)(k0 + 3) * C + n];
    uint2 hi, lo;
    split_pack2(v, hi, lo);
    uint32_t off = n * 256 + ((k0 * 2) ^ ((n & 7) << 4));
    *(uint2*)(g_wt + off)         = hi;
    *(uint2*)(g_wt + 32768 + off) = lo;
}

// SMEM layout (bytes). Row stride 256B, XOR swizzle byteoff ^ ((row&7)<<4).
#define SM_AH 0                  // A hi: 64 x 128 bf16 = 16 KB
#define SM_AL 16384              // A lo
#define SM_BH 32768              // Wt hi+lo contiguous 64 KB (mirrors g_wt)
#define SM_BL 65536
#define SM_TOTAL 98304           // 96 KB -> 2 CTAs / SM

// out[m,n] = sum_k x[m,k]*w[k,n]  (UNMASKED; k_apply zeroes deg-0 rows)
// 3-pass split-bf16: Ahi*Bhi + Ahi*Blo + Alo*Bhi (fp32 accum)
// R12 config (8 warps, 2x4) + cross-kstep fragment double-buffering: LDSMs for
// kstep s+1 issue before the 24 MMAs of kstep s, hiding LDS latency.
__global__ void __launch_bounds__(256, 2) k_tc(
    const float* __restrict__ x, float* __restrict__ out)
{
    extern __shared__ char smem[];
    const uint32_t sb = smem_u32(smem);
    const int tid = threadIdx.x;
    const int l   = tid & 31;
    const int wid = tid >> 5;
    const int wm  = wid >> 2;          // 0..1 : rows wm*32 ..
    const int wn  = wid & 3;           // 0..3 : cols wn*32 ..
    const int m0  = blockIdx.x * MT;

    // ---- B tile: flat async copy of pre-split/pre-swizzled Wt (64 KB)
    #pragma unroll
    for (int i = 0; i < 16; i++) {
        int c16 = tid + 256 * i;                  // 16B chunk index, 0..4095
        cp16(sb + SM_BH + c16 * 16, g_wt + c16 * 16);
    }
    asm volatile("cp.async.commit_group;" ::: "memory");

    // ---- A tile: coalesced f32 loads, split to bf16 hi/lo, swizzled store
    #pragma unroll
    for (int it = 0; it < 8; it++) {
        int i   = tid + 256 * it;
        int row = i >> 5;
        int c4  = i & 31;
        int gm  = m0 + row;
        float4 v = make_float4(0.f, 0.f, 0.f, 0.f);
        if (gm < NN) v = *(const float4*)(x + (size_t)gm * C + 4 * c4);
        uint2 hi, lo;
        split_pack2(v, hi, lo);
        uint32_t off = row * 256 + ((c4 * 8) ^ ((row & 7) << 4));
        *(uint2*)(smem + SM_AH + off) = hi;
        *(uint2*)(smem + SM_AL + off) = lo;
    }

    asm volatile("cp.async.wait_group 0;" ::: "memory");
    __syncthreads();

    // ---- per-lane ldmatrix address components
    const uint32_t aRow = (l & 7) + ((l >> 3) & 1) * 8;
    const uint32_t aK16 = (l >> 4) * 16;
    const uint32_t bN   = (l & 7) + ((l >> 4) & 1) * 8;
    const uint32_t bK16 = ((l >> 3) & 1) * 16;
    const uint32_t swz  = (l & 7) << 4;
    const uint32_t aOff0 = (wm * 32 + aRow) * 256;
    const uint32_t bOff0 = (wn * 32 + bN) * 256;

    float acc[2][4][4];
    #pragma unroll
    for (int mt = 0; mt < 2; mt++)
        #pragma unroll
        for (int nt = 0; nt < 4; nt++)
            #pragma unroll
            for (int i = 0; i < 4; i++) acc[mt][nt][i] = 0.f;

    // Fragment double buffers
    uint32_t ah[2][2][4], al[2][2][4], bh[2][2][4], bl[2][2][4];

    // Prologue: load fragments for kstep 0 into buffer 0
    {
        const uint32_t kbA = aK16 ^ swz;
        const uint32_t kbB = bK16 ^ swz;
        #pragma unroll
        for (int mt = 0; mt < 2; mt++) {
            uint32_t adr = sb + SM_AH + aOff0 + mt * 4096 + kbA;
            LDSM_X4(ah[0][mt], adr);
            LDSM_X4(al[0][mt], adr + (SM_AL - SM_AH));
        }
        #pragma unroll
        for (int np = 0; np < 2; np++) {
            uint32_t adr = sb + SM_BH + bOff0 + np * 4096 + kbB;
            LDSM_X4(bh[0][np], adr);
            LDSM_X4(bl[0][np], adr + (SM_BL - SM_BH));
        }
    }

    #pragma unroll
    for (int ks = 0; ks < 8; ks++) {
        const int cur = ks & 1;
        const int nxt = cur ^ 1;

        // Prefetch fragments for kstep ks+1 (retires under the MMAs below)
        if (ks < 7) {
            const uint32_t kbA = ((uint32_t)((ks + 1) * 32) + aK16) ^ swz;
            const uint32_t kbB = ((uint32_t)((ks + 1) * 32) + bK16) ^ swz;
            #pragma unroll
            for (int mt = 0; mt < 2; mt++) {
                uint32_t adr = sb + SM_AH + aOff0 + mt * 4096 + kbA;
                LDSM_X4(ah[nxt][mt], adr);
                LDSM_X4(al[nxt][mt], adr + (SM_AL - SM_AH));
            }
            #pragma unroll
            for (int np = 0; np < 2; np++) {
                uint32_t adr = sb + SM_BH + bOff0 + np * 4096 + kbB;
                LDSM_X4(bh[nxt][np], adr);
                LDSM_X4(bl[nxt][np], adr + (SM_BL - SM_BH));
            }
        }

        #pragma unroll
        for (int mt = 0; mt < 2; mt++)
            #pragma unroll
            for (int nt = 0; nt < 4; nt++) {
                uint32_t bh0 = bh[cur][nt >> 1][(nt & 1) * 2];
                uint32_t bh1 = bh[cur][nt >> 1][(nt & 1) * 2 + 1];
                uint32_t bl0 = bl[cur][nt >> 1][(nt & 1) * 2];
                uint32_t bl1 = bl[cur][nt >> 1][(nt & 1) * 2 + 1];
                mma16816(acc[mt][nt], ah[cur][mt], bh0, bh1);   // hi*hi
                mma16816(acc[mt][nt], ah[cur][mt], bl0, bl1);   // hi*lo
                mma16816(acc[mt][nt], al[cur][mt], bh0, bh1);   // lo*hi
            }
    }

    // ---- epilogue: store (no mask here; k_apply handles deg-0 rows)
    #pragma unroll
    for (int mt = 0; mt < 2; mt++) {
        int r0 = m0 + wm * 32 + mt * 16 + (l >> 2);
        int r1 = r0 + 8;
        #pragma unroll
        for (int nt = 0; nt < 4; nt++) {
            int colc = wn * 32 + nt * 8 + (l & 3) * 2;
            if (r0 < NN)
                *(float2*)(out + (size_t)r0 * C + colc) =
                    make_float2(acc[mt][nt][0], acc[mt][nt][1]);
            if (r1 < NN)
                *(float2*)(out + (size_t)r1 * C + colc) =
                    make_float2(acc[mt][nt][2], acc[mt][nt][3]);
        }
    }
}

extern "C" void kernel_launch(void* const* d_in, const int* in_sizes, int n_in,
                              void* d_out, int out_size) {
    // Identify inputs by element count (robust to metadata ordering):
    //   x: 12,800,000 f32 | weight: 16,384 f32 | att: 256 f32 (irrelevant —
    //   softmax weights sum to 1 over segments keyed identically to the
    //   message source, so attention collapses to an in-degree mask)
    //   edge_index: 3,200,000 int32
    const float* x = nullptr;
    const float* w = nullptr;
    const int*   ei = nullptr;
    for (int i = 0; i < n_in; i++) {
        if (in_sizes[i] == NN * C)      x  = (const float*)d_in[i];
        else if (in_sizes[i] == C * C)  w  = (const float*)d_in[i];
        else if (in_sizes[i] == 2 * NE) ei = (const int*)d_in[i];
    }
    const int* col = ei + NE;
    float* out = (float*)d_out;

    // One-time resources (no device memory allocation involved)
    static cudaStream_t s2;
    static cudaEvent_t ev_fork, ev_mark;
    static bool init = false;
    if (!init) {
        cudaFuncSetAttribute(k_tc, cudaFuncAttributeMaxDynamicSharedMemorySize,
                             SM_TOTAL);
        cudaStreamCreateWithFlags(&s2, cudaStreamNonBlocking);
        cudaEventCreateWithFlags(&ev_fork, cudaEventDisableTiming);
        cudaEventCreateWithFlags(&ev_mark, cudaEventDisableTiming);
        init = true;
    }

    // Fork: mark chain on s2, prep+GEMM on the main (capture) stream.
    cudaEventRecord(ev_fork, 0);
    cudaStreamWaitEvent(s2, ev_fork, 0);
    k_zero4<<<(NN / 4 + 255) / 256, 256, 0, s2>>>();
    k_mark<<<(NE + 255) / 256, 256, 0, s2>>>(col);
    cudaEventRecord(ev_mark, s2);

    k_prep<<<16, 256>>>(w);
    k_tc<<<NBLK, 256, SM_TOTAL>>>(x, out);

    // Join: apply in-degree mask after both the GEMM and the mark chain.
    cudaStreamWaitEvent(0, ev_mark, 0);
    k_apply<<<(NN + 255) / 256, 256>>>(out);
}

// round 17
// speedup vs baseline: 1.4090x; 1.0261x over previous
#include <cuda_runtime.h>
#include <cuda_bf16.h>
#include <cstdint>

#define NN 100000
#define NE 1600000
#define C  128        // IN_CH == HEADS*OUT_CH == 128
#define MT 64         // rows per CTA
#define NBLK ((NN + MT - 1) / MT)   // 1563

// ---------------- device globals ----------------
__device__ int g_mark[NN];
// W preformatted as mma.sync B fragments:
// layout: [(h*8 + s)*8 + nb2] blocks of 512B; block = 32 lanes x uint4
//   h: 0=hi,1=lo | s: kstep 0..7 | nb2: n16-pair 0..7
//   lane l uint4 = {b0,b1 of n8 block 2*nb2, b0,b1 of block 2*nb2+1}
__device__ __align__(16) char g_wtf[65536];

__global__ void k_zero4() {
    int i = blockIdx.x * 256 + threadIdx.x;
    if (i * 4 < NN) *(int4*)(g_mark + i * 4) = make_int4(0, 0, 0, 0);  // NN%4==0
}

__global__ void k_mark(const int* __restrict__ col) {
    int e = blockIdx.x * 256 + threadIdx.x;
    if (e < NE) {
        int n = col[e];
        if (n >= 0 && n < NN) g_mark[n] = 1;
    }
}

// Zero rows with zero in-degree (rare: ~0 rows expected). Joins mark + gemm.
__global__ void k_apply(float* __restrict__ out) {
    int n = blockIdx.x * 256 + threadIdx.x;
    if (n < NN && !g_mark[n]) {
        float4 z = make_float4(0.f, 0.f, 0.f, 0.f);
        float4* p = (float4*)(out + (size_t)n * C);
        #pragma unroll
        for (int i = 0; i < 32; i++) p[i] = z;
    }
}

// ---------------- helpers ----------------
__device__ __forceinline__ uint32_t smem_u32(const void* p) {
    uint32_t a;
    asm("{ .reg .u64 t; cvta.to.shared.u64 t, %1; cvt.u32.u64 %0, t; }"
        : "=r"(a) : "l"(p));
    return a;
}

#define LDSM_X4(r, addr) \
    asm volatile("ldmatrix.sync.aligned.m8n8.x4.shared.b16 {%0,%1,%2,%3}, [%4];" \
        : "=r"((r)[0]), "=r"((r)[1]), "=r"((r)[2]), "=r"((r)[3]) : "r"(addr))

__device__ __forceinline__ void mma16816(float* c, const uint32_t* a,
                                         uint32_t b0, uint32_t b1) {
    asm volatile(
        "mma.sync.aligned.m16n8k16.row.col.f32.bf16.bf16.f32 "
        "{%0,%1,%2,%3}, {%4,%5,%6,%7}, {%8,%9}, {%0,%1,%2,%3};"
        : "+f"(c[0]), "+f"(c[1]), "+f"(c[2]), "+f"(c[3])
        : "r"(a[0]), "r"(a[1]), "r"(a[2]), "r"(a[3]), "r"(b0), "r"(b1));
}

union BF2U { __nv_bfloat162 b; uint32_t u; };

__device__ __forceinline__ void split_pack2(float4 v, uint2& hi, uint2& lo) {
    __nv_bfloat16 h0 = __float2bfloat16(v.x), h1 = __float2bfloat16(v.y),
                  h2 = __float2bfloat16(v.z), h3 = __float2bfloat16(v.w);
    __nv_bfloat16 l0 = __float2bfloat16(v.x - __bfloat162float(h0));
    __nv_bfloat16 l1 = __float2bfloat16(v.y - __bfloat162float(h1));
    __nv_bfloat16 l2 = __float2bfloat16(v.z - __bfloat162float(h2));
    __nv_bfloat16 l3 = __float2bfloat16(v.w - __bfloat162float(h3));
    BF2U a, b, c, d;
    a.b = __nv_bfloat162(h0, h1); b.b = __nv_bfloat162(h2, h3);
    c.b = __nv_bfloat162(l0, l1); d.b = __nv_bfloat162(l2, l3);
    hi = make_uint2(a.u, b.u);
    lo = make_uint2(c.u, d.u);
}

// Preformat W into B fragments (4096 threads: h(2) x s(8) x nb2(8) x lane(32)).
__global__ void k_prep2(const float* __restrict__ w) {
    int idx = blockIdx.x * 256 + threadIdx.x;   // 0..4095
    int l   = idx & 31;
    int nb2 = (idx >> 5) & 7;
    int s   = (idx >> 8) & 7;
    int h   = idx >> 11;          // 0=hi, 1=lo
    int tig = l & 3, gid = l >> 2;
    int k0  = s * 16 + 2 * tig;
    int na  = nb2 * 16 + gid;     // n of first n8 block
    int nb  = na + 8;             // n of second n8 block

    auto grab = [&](int k, int n) -> __nv_bfloat16 {
        float v = w[(size_t)k * C + n];
        __nv_bfloat16 hi = __float2bfloat16(v);
        if (h == 0) return hi;
        return __float2bfloat16(v - __bfloat162float(hi));
    };
    auto pack = [&](__nv_bfloat16 x, __nv_bfloat16 y) -> uint32_t {
        BF2U u; u.b = __nv_bfloat162(x, y); return u.u;
    };

    uint32_t b0a = pack(grab(k0,     na), grab(k0 + 1, na));
    uint32_t b1a = pack(grab(k0 + 8, na), grab(k0 + 9, na));
    uint32_t b0b = pack(grab(k0,     nb), grab(k0 + 1, nb));
    uint32_t b1b = pack(grab(k0 + 8, nb), grab(k0 + 9, nb));

    *(uint4*)(g_wtf + (((h * 8 + s) * 8 + nb2) * 512) + l * 16) =
        make_uint4(b0a, b1a, b0b, b1b);
}

// SMEM: A only. Row stride 256B, XOR swizzle byteoff ^ ((row&7)<<4).
#define SM_AH 0                  // A hi: 64 x 128 bf16 = 16 KB
#define SM_AL 16384              // A lo
#define SM_TOTAL 32768           // 32 KB -> smem allows many CTAs; regs cap at 3

// out[m,n] = sum_k x[m,k]*w[k,n]  (UNMASKED; k_apply zeroes deg-0 rows)
// 3-pass split-bf16. A via ldmatrix from smem; B via LDG.128 of preformatted
// fragments (no sync dependency, L1-resident 64KB table).
__global__ void __launch_bounds__(256, 3) k_tc(
    const float* __restrict__ x, float* __restrict__ out)
{
    extern __shared__ char smem[];
    const uint32_t sb = smem_u32(smem);
    const int tid = threadIdx.x;
    const int l   = tid & 31;
    const int wid = tid >> 5;
    const int wm  = wid >> 2;          // 0..1 : rows wm*32 ..
    const int wn  = wid & 3;           // 0..3 : cols wn*32 ..
    const int m0  = blockIdx.x * MT;

    // ---- A tile: coalesced f32 loads, split to bf16 hi/lo, swizzled store
    #pragma unroll
    for (int it = 0; it < 8; it++) {
        int i   = tid + 256 * it;
        int row = i >> 5;
        int c4  = i & 31;
        int gm  = m0 + row;
        float4 v = make_float4(0.f, 0.f, 0.f, 0.f);
        if (gm < NN) v = *(const float4*)(x + (size_t)gm * C + 4 * c4);
        uint2 hi, lo;
        split_pack2(v, hi, lo);
        uint32_t off = row * 256 + ((c4 * 8) ^ ((row & 7) << 4));
        *(uint2*)(smem + SM_AH + off) = hi;
        *(uint2*)(smem + SM_AL + off) = lo;
    }
    __syncthreads();

    // ---- per-lane ldmatrix address components (A only)
    const uint32_t aRow = (l & 7) + ((l >> 3) & 1) * 8;
    const uint32_t aK16 = (l >> 4) * 16;
    const uint32_t swz  = (l & 7) << 4;
    const uint32_t aOff0 = (wm * 32 + aRow) * 256;

    // B fragment base pointers for this warp (lane-resolved)
    const char* wf  = g_wtf;
    const uint32_t wfl = (uint32_t)(2 * wn) * 512 + (uint32_t)l * 16;

    float acc[2][4][4];
    #pragma unroll
    for (int mt = 0; mt < 2; mt++)
        #pragma unroll
        for (int nt = 0; nt < 4; nt++)
            #pragma unroll
            for (int i = 0; i < 4; i++) acc[mt][nt][i] = 0.f;

    #pragma unroll
    for (int ks = 0; ks < 8; ks++) {
        // B fragments: 4 x LDG.128 (hi/lo x 2 n16-pairs), no sync dependency
        const uint4 BH0 = *(const uint4*)(wf + (uint32_t)(ks * 8) * 512 + wfl);
        const uint4 BH1 = *(const uint4*)(wf + (uint32_t)(ks * 8 + 1) * 512 + wfl);
        const uint4 BL0 = *(const uint4*)(wf + (uint32_t)((8 + ks) * 8) * 512 + wfl);
        const uint4 BL1 = *(const uint4*)(wf + (uint32_t)((8 + ks) * 8 + 1) * 512 + wfl);

        // A fragments via ldmatrix
        const uint32_t kbA = ((uint32_t)(ks * 32) + aK16) ^ swz;
        uint32_t ah[2][4], al[2][4];
        #pragma unroll
        for (int mt = 0; mt < 2; mt++) {
            uint32_t adr = sb + SM_AH + aOff0 + mt * 4096 + kbA;
            LDSM_X4(ah[mt], adr);
            LDSM_X4(al[mt], adr + (SM_AL - SM_AH));
        }

        const uint32_t bh0[4] = {BH0.x, BH0.z, BH1.x, BH1.z};
        const uint32_t bh1[4] = {BH0.y, BH0.w, BH1.y, BH1.w};
        const uint32_t bl0[4] = {BL0.x, BL0.z, BL1.x, BL1.z};
        const uint32_t bl1[4] = {BL0.y, BL0.w, BL1.y, BL1.w};

        #pragma unroll
        for (int mt = 0; mt < 2; mt++)
            #pragma unroll
            for (int nt = 0; nt < 4; nt++) {
                mma16816(acc[mt][nt], ah[mt], bh0[nt], bh1[nt]);   // hi*hi
                mma16816(acc[mt][nt], ah[mt], bl0[nt], bl1[nt]);   // hi*lo
                mma16816(acc[mt][nt], al[mt], bh0[nt], bh1[nt]);   // lo*hi
            }
    }

    // ---- epilogue: store (no mask here; k_apply handles deg-0 rows)
    #pragma unroll
    for (int mt = 0; mt < 2; mt++) {
        int r0 = m0 + wm * 32 + mt * 16 + (l >> 2);
        int r1 = r0 + 8;
        #pragma unroll
        for (int nt = 0; nt < 4; nt++) {
            int colc = wn * 32 + nt * 8 + (l & 3) * 2;
            if (r0 < NN)
                *(float2*)(out + (size_t)r0 * C + colc) =
                    make_float2(acc[mt][nt][0], acc[mt][nt][1]);
            if (r1 < NN)
                *(float2*)(out + (size_t)r1 * C + colc) =
                    make_float2(acc[mt][nt][2], acc[mt][nt][3]);
        }
    }
}

extern "C" void kernel_launch(void* const* d_in, const int* in_sizes, int n_in,
                              void* d_out, int out_size) {
    // Identify inputs by element count (robust to metadata ordering):
    //   x: 12,800,000 f32 | weight: 16,384 f32 | att: 256 f32 (irrelevant —
    //   softmax weights sum to 1 over segments keyed identically to the
    //   message source, so attention collapses to an in-degree mask)
    //   edge_index: 3,200,000 int32
    const float* x = nullptr;
    const float* w = nullptr;
    const int*   ei = nullptr;
    for (int i = 0; i < n_in; i++) {
        if (in_sizes[i] == NN * C)      x  = (const float*)d_in[i];
        else if (in_sizes[i] == C * C)  w  = (const float*)d_in[i];
        else if (in_sizes[i] == 2 * NE) ei = (const int*)d_in[i];
    }
    const int* col = ei + NE;
    float* out = (float*)d_out;

    // One-time resources (no device memory allocation involved)
    static cudaStream_t s2;
    static cudaEvent_t ev_fork, ev_mark;
    static bool init = false;
    if (!init) {
        cudaFuncSetAttribute(k_tc, cudaFuncAttributeMaxDynamicSharedMemorySize,
                             SM_TOTAL);
        cudaStreamCreateWithFlags(&s2, cudaStreamNonBlocking);
        cudaEventCreateWithFlags(&ev_fork, cudaEventDisableTiming);
        cudaEventCreateWithFlags(&ev_mark, cudaEventDisableTiming);
        init = true;
    }

    // Fork: mark chain on s2, prep+GEMM on the main (capture) stream.
    cudaEventRecord(ev_fork, 0);
    cudaStreamWaitEvent(s2, ev_fork, 0);
    k_zero4<<<(NN / 4 + 255) / 256, 256, 0, s2>>>();
    k_mark<<<(NE + 255) / 256, 256, 0, s2>>>(col);
    cudaEventRecord(ev_mark, s2);

    k_prep2<<<16, 256>>>(w);
    k_tc<<<NBLK, 256, SM_TOTAL>>>(x, out);

    // Join: apply in-degree mask after both the GEMM and the mark chain.
    cudaStreamWaitEvent(0, ev_mark, 0);
    k_apply<<<(NN + 255) / 256, 256>>>(out);
}